// round 13
// baseline (speedup 1.0000x reference)
#include <cuda_runtime.h>
#include <cuda_fp16.h>
#include <cstdint>
#include <math.h>

// ---------------- problem constants ----------------
#define BB   4
#define NX   4096
#define NY   8192
#define DD   256
#define TMR  128                 // x rows per CTA
#define TNC  128                 // y cols per tile
#define KCH  64                  // k per chunk (fp16: 128B row)
#define NTIL (NY / TNC)          // 64 y tiles
#define NCHK (DD / KCH)          // 4 chunks per tile
#define CHTOT (NTIL * NCHK)      // 256 chunk iterations
#define KK   10
#define NVAL (BB * NX * KK)      // 163840
#define INV_TAU 20.0f
#define NTHR 512
#define BLKB 16384               // bytes per block (128 rows x 64 k x 2B)

// blocked + swizzled fp16-split scratch (same layout as R12)
__device__ __align__(128) __half g_xh[(size_t)BB * NX * DD];
__device__ __align__(128) __half g_xl[(size_t)BB * NX * DD];
__device__ __align__(128) __half g_yh[(size_t)BB * NY * DD];
__device__ __align__(128) __half g_yl[(size_t)BB * NY * DD];

// ---------------- smem layout (bytes) ----------------
#define STG_SZ  65536
#define OFF_XH  0
#define OFF_XL  16384
#define OFF_YH  32768
#define OFF_YL  49152
#define SM_SIM  131072               // 64 x 133 floats = 34048
#define SM_LV   165120
#define SM_LI   170240
#define SM_CTRL 175360               // full0,full1,free0,free1
#define SM_TOT  175424
#define SIMP    133

// ---------------- helpers ----------------
static __device__ __forceinline__ uint32_t cvta_s(const void* p) {
    return (uint32_t)__cvta_generic_to_shared(p);
}
static __device__ __forceinline__ uint32_t lds32(uint32_t a) {
    uint32_t v;
    asm volatile("ld.shared.b32 %0, [%1];" : "=r"(v) : "r"(a));
    return v;
}
static __device__ __forceinline__ void bulk16k(uint32_t dst, const void* src, uint32_t mbar) {
    asm volatile(
        "cp.async.bulk.shared::cta.global.mbarrier::complete_tx::bytes [%0], [%1], %2, [%3];"
        :: "r"(dst), "l"(src), "r"(16384u), "r"(mbar) : "memory");
}
static __device__ __forceinline__ void mb_init(uint32_t a, uint32_t c) {
    asm volatile("mbarrier.init.shared.b64 [%0], %1;" :: "r"(a), "r"(c) : "memory");
}
static __device__ __forceinline__ void mb_expect(uint32_t a, uint32_t bytes) {
    asm volatile("mbarrier.arrive.expect_tx.shared.b64 _, [%0], %1;" :: "r"(a), "r"(bytes) : "memory");
}
static __device__ __forceinline__ void mb_arrive(uint32_t a) {
    asm volatile("mbarrier.arrive.shared.b64 _, [%0];" :: "r"(a) : "memory");
}
static __device__ __forceinline__ void mb_wait(uint32_t a, uint32_t par) {
    asm volatile(
        "{\n\t.reg .pred P;\n\t"
        "WL%=:\n\t"
        "mbarrier.try_wait.parity.acquire.cta.shared::cta.b64 P, [%0], %1, 0x989680;\n\t"
        "@P bra WD%=;\n\t"
        "bra WL%=;\n\t"
        "WD%=:\n\t}"
        :: "r"(a), "r"(par) : "memory");
}
static __device__ __forceinline__ void mma16f(float* d, const uint32_t* a,
                                              uint32_t b0, uint32_t b1) {
    asm volatile(
        "mma.sync.aligned.m16n8k16.row.col.f32.f16.f16.f32 "
        "{%0,%1,%2,%3}, {%4,%5,%6,%7}, {%8,%9}, {%0,%1,%2,%3};"
        : "+f"(d[0]), "+f"(d[1]), "+f"(d[2]), "+f"(d[3])
        : "r"(a[0]), "r"(a[1]), "r"(a[2]), "r"(a[3]), "r"(b0), "r"(b1));
}

// ---------------- kernel 1: normalize + fp16-split + blocked/swizzled store ----------------
__global__ void norm_split_kernel(const float* __restrict__ fx, const float* __restrict__ fy) {
    int wid  = (blockIdx.x * blockDim.x + threadIdx.x) >> 5;
    int lane = threadIdx.x & 31;
    const int totx = BB * NX;
    if (wid >= totx + BB * NY) return;

    const float* src;
    __half *dh, *dl;
    int blk0, rit;
    if (wid < totx) {
        int b = wid / NX, r = wid % NX;
        src = fx + (size_t)wid * DD;
        dh = g_xh; dl = g_xl;
        blk0 = (b * 32 + (r >> 7)) * 4;
        rit = r & 127;
    } else {
        int r0 = wid - totx;
        int b = r0 / NY, r = r0 % NY;
        src = fy + (size_t)r0 * DD;
        dh = g_yh; dl = g_yl;
        blk0 = (b * 64 + (r >> 7)) * 4;
        rit = r & 127;
    }
    float4 a = ((const float4*)src)[lane];
    float4 b4 = ((const float4*)src)[lane + 32];
    float s = a.x*a.x + a.y*a.y + a.z*a.z + a.w*a.w
            + b4.x*b4.x + b4.y*b4.y + b4.z*b4.z + b4.w*b4.w;
#pragma unroll
    for (int off = 16; off > 0; off >>= 1) s += __shfl_xor_sync(0xffffffffu, s, off);
    float inv = 1.0f / fmaxf(sqrtf(s), 1e-12f);

    float va[4] = {a.x*inv, a.y*inv, a.z*inv, a.w*inv};
    float vb[4] = {b4.x*inv, b4.y*inv, b4.z*inv, b4.w*inv};

    __half ha[4], la[4], hb[4], lb[4];
#pragma unroll
    for (int i = 0; i < 4; i++) {
        ha[i] = __float2half_rn(va[i]);
        la[i] = __float2half_rn(va[i] - __half2float(ha[i]));
        hb[i] = __float2half_rn(vb[i]);
        lb[i] = __float2half_rn(vb[i] - __half2float(hb[i]));
    }

    int kw  = (4 * lane) & 63;
    int u   = kw >> 3;
    int hoff = kw & 7;
    size_t slotA = (size_t)(blk0 + (lane >> 4)) * 8192
                 + rit * 64 + (size_t)((u ^ (rit & 7)) * 8 + hoff);
    size_t slotB = (size_t)(blk0 + 2 + (lane >> 4)) * 8192
                 + rit * 64 + (size_t)((u ^ (rit & 7)) * 8 + hoff);

    uint2 wha, wla, whb, wlb;
    {
        __half2 p0 = __halves2half2(ha[0], ha[1]);
        __half2 p1 = __halves2half2(ha[2], ha[3]);
        wha.x = *(uint32_t*)&p0; wha.y = *(uint32_t*)&p1;
        p0 = __halves2half2(la[0], la[1]); p1 = __halves2half2(la[2], la[3]);
        wla.x = *(uint32_t*)&p0; wla.y = *(uint32_t*)&p1;
        p0 = __halves2half2(hb[0], hb[1]); p1 = __halves2half2(hb[2], hb[3]);
        whb.x = *(uint32_t*)&p0; whb.y = *(uint32_t*)&p1;
        p0 = __halves2half2(lb[0], lb[1]); p1 = __halves2half2(lb[2], lb[3]);
        wlb.x = *(uint32_t*)&p0; wlb.y = *(uint32_t*)&p1;
    }
    *(uint2*)((char*)dh + slotA * 2) = wha;
    *(uint2*)((char*)dl + slotA * 2) = wla;
    *(uint2*)((char*)dh + slotB * 2) = whb;
    *(uint2*)((char*)dl + slotB * 2) = wlb;
}

// ---------------- kernel 2: 512-thread pipelined fp16 3-pass GEMM + top-k ----------------
extern __shared__ unsigned char smem_raw[];

// fragment loader for 32x32 warp tile: 8 A regs (2 m-frags) + 8 B regs (4 n-frags)
static __device__ __forceinline__ void load_frags(
    uint32_t A, uint32_t Bq, int ks,
    uint32_t abase, uint32_t key, const uint32_t* bbase,
    uint32_t afr[2][4], uint32_t bfr[4][2])
{
    const uint32_t u0 = (uint32_t)((2 * ks) ^ key) << 4;
    const uint32_t u1 = (uint32_t)((2 * ks + 1) ^ key) << 4;
#pragma unroll
    for (int m = 0; m < 2; m++) {
        uint32_t ab = A + abase + (uint32_t)(m * 16 * 128);
        afr[m][0] = lds32(ab + u0);
        afr[m][1] = lds32(ab + 8 * 128 + u0);
        afr[m][2] = lds32(ab + u1);
        afr[m][3] = lds32(ab + 8 * 128 + u1);
    }
#pragma unroll
    for (int n = 0; n < 4; n++) {
        bfr[n][0] = lds32(Bq + bbase[n] + u0);
        bfr[n][1] = lds32(Bq + bbase[n] + u1);
    }
}

__global__ void __launch_bounds__(NTHR, 1)
sim_mma_kernel(float* __restrict__ out, int out_size) {
    const int b    = blockIdx.y;
    const int xt   = blockIdx.x;
    const int tid  = threadIdx.x;
    const int wid  = tid >> 5, lane = tid & 31;
    const int warpM = wid & 3;           // 4 warps along M (32 rows each)
    const int warpN = wid >> 2;          // 4 warps along N (32 cols each)
    const int gid  = lane >> 2;
    const int tig  = lane & 3;

    uint32_t s0 = cvta_s(smem_raw);
    float* SIM = (float*)(smem_raw + SM_SIM);
    float* LV  = (float*)(smem_raw + SM_LV);
    int*   LI  = (int*)(smem_raw + SM_LI);
    const uint32_t full0 = s0 + SM_CTRL,      full1 = s0 + SM_CTRL + 8;
    const uint32_t free0 = s0 + SM_CTRL + 16, free1 = s0 + SM_CTRL + 24;

    for (int i = tid; i < TMR * KK; i += NTHR) { LV[i] = -1e38f; LI[i] = 0; }
    if (tid == 0) {
        mb_init(full0, 1); mb_init(full1, 1);
        mb_init(free0, 16); mb_init(free1, 16);
    }
    __syncthreads();

    const int xblk0 = (b * 32 + xt) * 4;
    const int yblk0 = b * 64 * 4;

    uint32_t abase = (uint32_t)((warpM * 32 + gid) * 128 + tig * 4);
    const uint32_t key = (uint32_t)(gid & 7);
    uint32_t bbase[4];
#pragma unroll
    for (int n = 0; n < 4; n++)
        bbase[n] = (uint32_t)((warpN * 32 + n * 8 + gid) * 128 + tig * 4);

    float acc[2][4][4];

    if (tid == 0) {
        mb_expect(full0, 65536);
        bulk16k(s0 + OFF_XH, (const char*)g_xh + (size_t)xblk0 * BLKB, full0);
        bulk16k(s0 + OFF_XL, (const char*)g_xl + (size_t)xblk0 * BLKB, full0);
        bulk16k(s0 + OFF_YH, (const char*)g_yh + (size_t)yblk0 * BLKB, full0);
        bulk16k(s0 + OFF_YL, (const char*)g_yl + (size_t)yblk0 * BLKB, full0);
    }

    for (int cc = 0; cc < CHTOT; cc++) {
        const int buf = cc & 1;
        const int c = cc & 3, t = cc >> 2;

        mb_wait(buf ? full1 : full0, (uint32_t)((cc >> 1) & 1));

        if (cc + 1 < CHTOT && tid == 0) {
            int nb = (cc + 1) & 1;
            int fi = (cc + 1) >> 1;
            if (fi >= 1) mb_wait(nb ? free1 : free0, (uint32_t)((fi - 1) & 1));
            int tn = (cc + 1) >> 2, cn = (cc + 1) & 3;
            uint32_t sb = s0 + (uint32_t)(nb * STG_SZ);
            uint32_t mbn = nb ? full1 : full0;
            mb_expect(mbn, 65536);
            bulk16k(sb + OFF_XH, (const char*)g_xh + (size_t)(xblk0 + cn) * BLKB, mbn);
            bulk16k(sb + OFF_XL, (const char*)g_xl + (size_t)(xblk0 + cn) * BLKB, mbn);
            bulk16k(sb + OFF_YH, (const char*)g_yh + (size_t)(yblk0 + tn * 4 + cn) * BLKB, mbn);
            bulk16k(sb + OFF_YL, (const char*)g_yl + (size_t)(yblk0 + tn * 4 + cn) * BLKB, mbn);
        }

        if (c == 0) {
#pragma unroll
            for (int m = 0; m < 2; m++)
#pragma unroll
                for (int n = 0; n < 4; n++)
#pragma unroll
                    for (int j = 0; j < 4; j++) acc[m][n][j] = 0.0f;
        }

        const uint32_t sb = s0 + (uint32_t)(buf * STG_SZ);
        const uint32_t Ab[3]  = {sb + OFF_XH, sb + OFF_XH, sb + OFF_XL};
        const uint32_t Bbs[3] = {sb + OFF_YH, sb + OFF_YL, sb + OFF_YH};

        // flat 12-step loop (3 pass x 4 ks), fragments double-buffered
        uint32_t afr[2][2][4], bfr[2][4][2];
        load_frags(Ab[0], Bbs[0], 0, abase, key, bbase, afr[0], bfr[0]);
#pragma unroll
        for (int s = 0; s < 12; s++) {
            const int d = s & 1;
            if (s < 11) {
                const int sn = s + 1;
                load_frags(Ab[sn >> 2], Bbs[sn >> 2], sn & 3,
                           abase, key, bbase, afr[sn & 1], bfr[sn & 1]);
            }
#pragma unroll
            for (int m = 0; m < 2; m++)
#pragma unroll
                for (int n = 0; n < 4; n++)
                    mma16f(acc[m][n], afr[d][m], bfr[d][n][0], bfr[d][n][1]);
        }

        if (lane == 0) mb_arrive(buf ? free1 : free0);

        // tile complete: stage SIM halves + top-k scan
        if (c == 3) {
            const int col0 = t * TNC;
#pragma unroll
            for (int h = 0; h < 2; h++) {
                if ((warpM >> 1) == h) {
#pragma unroll
                    for (int m = 0; m < 2; m++) {
                        int r0 = (warpM & 1) * 32 + m * 16 + gid;
#pragma unroll
                        for (int n = 0; n < 4; n++) {
                            int col = warpN * 32 + n * 8 + 2 * tig;
                            SIM[r0 * SIMP + col]           = acc[m][n][0];
                            SIM[r0 * SIMP + col + 1]       = acc[m][n][1];
                            SIM[(r0 + 8) * SIMP + col]     = acc[m][n][2];
                            SIM[(r0 + 8) * SIMP + col + 1] = acc[m][n][3];
                        }
                    }
                }
                __syncthreads();
                if (tid < 64) {
                    int row = h * 64 + tid;
                    float* lv = LV + row * KK;
                    int*   li = LI + row * KK;
                    const float* srow = SIM + tid * SIMP;
                    float lv9 = lv[KK - 1];
#pragma unroll 4
                    for (int cL = 0; cL < TNC; cL++) {
                        float vv = srow[cL];
                        if (vv > lv9) {
                            int p = KK - 1;
                            while (p > 0 && lv[p - 1] < vv) {
                                lv[p] = lv[p - 1]; li[p] = li[p - 1]; --p;
                            }
                            lv[p] = vv; li[p] = col0 + cL;
                            lv9 = lv[KK - 1];
                        }
                    }
                }
                __syncthreads();
            }
        }
    }

    // ---- finalize: softmax + sort-by-col + write ----
    if (tid < TMR) {
        float v[KK]; int ix[KK];
#pragma unroll
        for (int k = 0; k < KK; k++) { v[k] = LV[tid * KK + k]; ix[k] = LI[tid * KK + k]; }
        float m = v[0];
        float e[KK]; float ssum = 0.0f;
#pragma unroll
        for (int k = 0; k < KK; k++) { e[k] = expf((v[k] - m) * INV_TAU); ssum += e[k]; }
        float inv = 1.0f / ssum;
#pragma unroll
        for (int a = 1; a < KK; a++) {
            int ki = ix[a]; float ke = e[a]; int p = a;
            while (p > 0 && ix[p - 1] > ki) { ix[p] = ix[p - 1]; e[p] = e[p - 1]; --p; }
            ix[p] = ki; e[p] = ke;
        }
        int gRow = xt * TMR + tid;
        size_t basev = ((size_t)b * NX + gRow) * KK;
        bool write_idx = (out_size >= 4 * NVAL);
#pragma unroll
        for (int k = 0; k < KK; k++) {
            out[basev + k] = e[k] * inv;
            if (write_idx) {
                out[(size_t)NVAL     + basev + k] = (float)b;
                out[(size_t)2 * NVAL + basev + k] = (float)gRow;
                out[(size_t)3 * NVAL + basev + k] = (float)ix[k];
            }
        }
    }
}

// ---------------- launch ----------------
extern "C" void kernel_launch(void* const* d_in, const int* in_sizes, int n_in,
                              void* d_out, int out_size) {
    const float* fx = (const float*)d_in[0];
    const float* fy = (const float*)d_in[1];
    float* out = (float*)d_out;

    int nrows = BB * NX + BB * NY;
    norm_split_kernel<<<(nrows + 7) / 8, 256>>>(fx, fy);

    cudaFuncSetAttribute(sim_mma_kernel,
                         cudaFuncAttributeMaxDynamicSharedMemorySize, SM_TOT);
    dim3 g2(NX / TMR, BB);                     // 128 CTAs
    sim_mma_kernel<<<g2, NTHR, SM_TOT>>>(out, out_size);
}

// round 14
// speedup vs baseline: 1.5064x; 1.5064x over previous
#include <cuda_runtime.h>
#include <cuda_fp16.h>
#include <cstdint>
#include <math.h>

// ---------------- problem constants ----------------
#define BB   4
#define NX   4096
#define NY   8192
#define DD   256
#define TMR  128                 // x rows per CTA
#define TNC  128                 // y cols per tile
#define KCH  64                  // k per chunk (fp16: 128B row)
#define NTIL (NY / TNC)          // 64 y tiles
#define NCHK (DD / KCH)          // 4 chunks per tile
#define CHTOT (NTIL * NCHK)      // 256 chunk iterations
#define KK   10
#define NVAL (BB * NX * KK)      // 163840
#define INV_TAU 20.0f
#define NTHR 256
#define BLKB 16384               // bytes per block (128 rows x 64 k x 2B)

// blocked + swizzled fp16-split scratch (same layout as R12)
__device__ __align__(128) __half g_xh[(size_t)BB * NX * DD];
__device__ __align__(128) __half g_xl[(size_t)BB * NX * DD];
__device__ __align__(128) __half g_yh[(size_t)BB * NY * DD];
__device__ __align__(128) __half g_yl[(size_t)BB * NY * DD];

// ---------------- smem layout (bytes) ----------------
#define STG_SZ  65536
#define OFF_XH  0
#define OFF_XL  16384
#define OFF_YH  32768
#define OFF_YL  49152
#define SM_SIM  131072               // 128 x 132 floats = 67584
#define SM_LV   198656               // 128*10*4 = 5120
#define SM_LI   203776               // 5120
#define SM_CTRL 208896               // full0,full1,free0,free1
#define SM_TOT  208960
#define SIMP    132

// ---------------- helpers ----------------
static __device__ __forceinline__ uint32_t cvta_s(const void* p) {
    return (uint32_t)__cvta_generic_to_shared(p);
}
static __device__ __forceinline__ uint32_t lds32(uint32_t a) {
    uint32_t v;
    asm volatile("ld.shared.b32 %0, [%1];" : "=r"(v) : "r"(a));
    return v;
}
static __device__ __forceinline__ void bulk16k(uint32_t dst, const void* src, uint32_t mbar) {
    asm volatile(
        "cp.async.bulk.shared::cta.global.mbarrier::complete_tx::bytes [%0], [%1], %2, [%3];"
        :: "r"(dst), "l"(src), "r"(16384u), "r"(mbar) : "memory");
}
static __device__ __forceinline__ void mb_init(uint32_t a, uint32_t c) {
    asm volatile("mbarrier.init.shared.b64 [%0], %1;" :: "r"(a), "r"(c) : "memory");
}
static __device__ __forceinline__ void mb_expect(uint32_t a, uint32_t bytes) {
    asm volatile("mbarrier.arrive.expect_tx.shared.b64 _, [%0], %1;" :: "r"(a), "r"(bytes) : "memory");
}
static __device__ __forceinline__ void mb_arrive(uint32_t a) {
    asm volatile("mbarrier.arrive.shared.b64 _, [%0];" :: "r"(a) : "memory");
}
static __device__ __forceinline__ void mb_wait(uint32_t a, uint32_t par) {
    asm volatile(
        "{\n\t.reg .pred P;\n\t"
        "WL%=:\n\t"
        "mbarrier.try_wait.parity.acquire.cta.shared::cta.b64 P, [%0], %1, 0x989680;\n\t"
        "@P bra WD%=;\n\t"
        "bra WL%=;\n\t"
        "WD%=:\n\t}"
        :: "r"(a), "r"(par) : "memory");
}
static __device__ __forceinline__ void mma16f(float* d, const uint32_t* a,
                                              uint32_t b0, uint32_t b1) {
    asm volatile(
        "mma.sync.aligned.m16n8k16.row.col.f32.f16.f16.f32 "
        "{%0,%1,%2,%3}, {%4,%5,%6,%7}, {%8,%9}, {%0,%1,%2,%3};"
        : "+f"(d[0]), "+f"(d[1]), "+f"(d[2]), "+f"(d[3])
        : "r"(a[0]), "r"(a[1]), "r"(a[2]), "r"(a[3]), "r"(b0), "r"(b1));
}

// ---------------- kernel 1: normalize + fp16-split + blocked/swizzled store ----------------
__global__ void norm_split_kernel(const float* __restrict__ fx, const float* __restrict__ fy) {
    int wid  = (blockIdx.x * blockDim.x + threadIdx.x) >> 5;
    int lane = threadIdx.x & 31;
    const int totx = BB * NX;
    if (wid >= totx + BB * NY) return;

    const float* src;
    __half *dh, *dl;
    int blk0, rit;
    if (wid < totx) {
        int b = wid / NX, r = wid % NX;
        src = fx + (size_t)wid * DD;
        dh = g_xh; dl = g_xl;
        blk0 = (b * 32 + (r >> 7)) * 4;
        rit = r & 127;
    } else {
        int r0 = wid - totx;
        int b = r0 / NY, r = r0 % NY;
        src = fy + (size_t)r0 * DD;
        dh = g_yh; dl = g_yl;
        blk0 = (b * 64 + (r >> 7)) * 4;
        rit = r & 127;
    }
    float4 a = ((const float4*)src)[lane];
    float4 b4 = ((const float4*)src)[lane + 32];
    float s = a.x*a.x + a.y*a.y + a.z*a.z + a.w*a.w
            + b4.x*b4.x + b4.y*b4.y + b4.z*b4.z + b4.w*b4.w;
#pragma unroll
    for (int off = 16; off > 0; off >>= 1) s += __shfl_xor_sync(0xffffffffu, s, off);
    float inv = 1.0f / fmaxf(sqrtf(s), 1e-12f);

    float va[4] = {a.x*inv, a.y*inv, a.z*inv, a.w*inv};
    float vb[4] = {b4.x*inv, b4.y*inv, b4.z*inv, b4.w*inv};

    __half ha[4], la[4], hb[4], lb[4];
#pragma unroll
    for (int i = 0; i < 4; i++) {
        ha[i] = __float2half_rn(va[i]);
        la[i] = __float2half_rn(va[i] - __half2float(ha[i]));
        hb[i] = __float2half_rn(vb[i]);
        lb[i] = __float2half_rn(vb[i] - __half2float(hb[i]));
    }

    int kw  = (4 * lane) & 63;
    int u   = kw >> 3;
    int hoff = kw & 7;
    size_t slotA = (size_t)(blk0 + (lane >> 4)) * 8192
                 + rit * 64 + (size_t)((u ^ (rit & 7)) * 8 + hoff);
    size_t slotB = (size_t)(blk0 + 2 + (lane >> 4)) * 8192
                 + rit * 64 + (size_t)((u ^ (rit & 7)) * 8 + hoff);

    uint2 wha, wla, whb, wlb;
    {
        __half2 p0 = __halves2half2(ha[0], ha[1]);
        __half2 p1 = __halves2half2(ha[2], ha[3]);
        wha.x = *(uint32_t*)&p0; wha.y = *(uint32_t*)&p1;
        p0 = __halves2half2(la[0], la[1]); p1 = __halves2half2(la[2], la[3]);
        wla.x = *(uint32_t*)&p0; wla.y = *(uint32_t*)&p1;
        p0 = __halves2half2(hb[0], hb[1]); p1 = __halves2half2(hb[2], hb[3]);
        whb.x = *(uint32_t*)&p0; whb.y = *(uint32_t*)&p1;
        p0 = __halves2half2(lb[0], lb[1]); p1 = __halves2half2(lb[2], lb[3]);
        wlb.x = *(uint32_t*)&p0; wlb.y = *(uint32_t*)&p1;
    }
    *(uint2*)((char*)dh + slotA * 2) = wha;
    *(uint2*)((char*)dl + slotA * 2) = wla;
    *(uint2*)((char*)dh + slotB * 2) = whb;
    *(uint2*)((char*)dl + slotB * 2) = wlb;
}

// ---------------- kernel 2: pipelined fp16 3-pass GEMM + ballot top-k ----------------
extern __shared__ unsigned char smem_raw[];

static __device__ __forceinline__ void load_frags(
    uint32_t A, uint32_t Bq, int ks,
    uint32_t abase, uint32_t key, const uint32_t* bbase,
    uint32_t afr[4][4], uint32_t bfr[4][2])
{
    const uint32_t u0 = (uint32_t)((2 * ks) ^ key) << 4;
    const uint32_t u1 = (uint32_t)((2 * ks + 1) ^ key) << 4;
#pragma unroll
    for (int m = 0; m < 4; m++) {
        uint32_t ab = A + abase + (uint32_t)(m * 16 * 128);
        afr[m][0] = lds32(ab + u0);
        afr[m][1] = lds32(ab + 8 * 128 + u0);
        afr[m][2] = lds32(ab + u1);
        afr[m][3] = lds32(ab + 8 * 128 + u1);
    }
#pragma unroll
    for (int n = 0; n < 4; n++) {
        bfr[n][0] = lds32(Bq + bbase[n] + u0);
        bfr[n][1] = lds32(Bq + bbase[n] + u1);
    }
}

__global__ void __launch_bounds__(NTHR, 1)
sim_mma_kernel(float* __restrict__ out, int out_size) {
    const int b    = blockIdx.y;
    const int xt   = blockIdx.x;
    const int tid  = threadIdx.x;
    const int wid  = tid >> 5, lane = tid & 31;
    const int warpM = wid & 1;           // 2 warps along M (64 rows each)
    const int warpN = wid >> 1;          // 4 warps along N (32 cols each)
    const int gid  = lane >> 2;
    const int tig  = lane & 3;

    uint32_t s0 = cvta_s(smem_raw);
    float* SIM = (float*)(smem_raw + SM_SIM);
    float* LV  = (float*)(smem_raw + SM_LV);
    int*   LI  = (int*)(smem_raw + SM_LI);
    const uint32_t full0 = s0 + SM_CTRL,      full1 = s0 + SM_CTRL + 8;
    const uint32_t free0 = s0 + SM_CTRL + 16, free1 = s0 + SM_CTRL + 24;

    for (int i = tid; i < TMR * KK; i += NTHR) { LV[i] = -1e38f; LI[i] = 0; }
    if (tid == 0) {
        mb_init(full0, 1); mb_init(full1, 1);
        mb_init(free0, 8); mb_init(free1, 8);
    }
    __syncthreads();

    const int xblk0 = (b * 32 + xt) * 4;
    const int yblk0 = b * 64 * 4;

    uint32_t abase = (uint32_t)((warpM * 64 + gid) * 128 + tig * 4);
    const uint32_t key = (uint32_t)(gid & 7);
    uint32_t bbase[4];
#pragma unroll
    for (int n = 0; n < 4; n++)
        bbase[n] = (uint32_t)((warpN * 32 + n * 8 + gid) * 128 + tig * 4);

    float acc[4][4][4];

    if (tid == 0) {
        mb_expect(full0, 65536);
        bulk16k(s0 + OFF_XH, (const char*)g_xh + (size_t)xblk0 * BLKB, full0);
        bulk16k(s0 + OFF_XL, (const char*)g_xl + (size_t)xblk0 * BLKB, full0);
        bulk16k(s0 + OFF_YH, (const char*)g_yh + (size_t)yblk0 * BLKB, full0);
        bulk16k(s0 + OFF_YL, (const char*)g_yl + (size_t)yblk0 * BLKB, full0);
    }

    for (int cc = 0; cc < CHTOT; cc++) {
        const int buf = cc & 1;
        const int c = cc & 3, t = cc >> 2;

        mb_wait(buf ? full1 : full0, (uint32_t)((cc >> 1) & 1));

        if (cc + 1 < CHTOT && tid == 0) {
            int nb = (cc + 1) & 1;
            int fi = (cc + 1) >> 1;
            if (fi >= 1) mb_wait(nb ? free1 : free0, (uint32_t)((fi - 1) & 1));
            int tn = (cc + 1) >> 2, cn = (cc + 1) & 3;
            uint32_t sb = s0 + (uint32_t)(nb * STG_SZ);
            uint32_t mbn = nb ? full1 : full0;
            mb_expect(mbn, 65536);
            bulk16k(sb + OFF_XH, (const char*)g_xh + (size_t)(xblk0 + cn) * BLKB, mbn);
            bulk16k(sb + OFF_XL, (const char*)g_xl + (size_t)(xblk0 + cn) * BLKB, mbn);
            bulk16k(sb + OFF_YH, (const char*)g_yh + (size_t)(yblk0 + tn * 4 + cn) * BLKB, mbn);
            bulk16k(sb + OFF_YL, (const char*)g_yl + (size_t)(yblk0 + tn * 4 + cn) * BLKB, mbn);
        }

        if (c == 0) {
#pragma unroll
            for (int m = 0; m < 4; m++)
#pragma unroll
                for (int n = 0; n < 4; n++)
#pragma unroll
                    for (int j = 0; j < 4; j++) acc[m][n][j] = 0.0f;
        }

        const uint32_t sb = s0 + (uint32_t)(buf * STG_SZ);
        const uint32_t Ab[3]  = {sb + OFF_XH, sb + OFF_XH, sb + OFF_XL};
        const uint32_t Bbs[3] = {sb + OFF_YH, sb + OFF_YL, sb + OFF_YH};

        // flat 12-step loop (3 pass x 4 ks), fragments double-buffered
        uint32_t afr[2][4][4], bfr[2][4][2];
        load_frags(Ab[0], Bbs[0], 0, abase, key, bbase, afr[0], bfr[0]);
#pragma unroll
        for (int s = 0; s < 12; s++) {
            const int d = s & 1;
            if (s < 11) {
                const int sn = s + 1;
                load_frags(Ab[sn >> 2], Bbs[sn >> 2], sn & 3,
                           abase, key, bbase, afr[sn & 1], bfr[sn & 1]);
            }
#pragma unroll
            for (int m = 0; m < 4; m++)
#pragma unroll
                for (int n = 0; n < 4; n++)
                    mma16f(acc[m][n], afr[d][m], bfr[d][n][0], bfr[d][n][1]);
        }

        if (lane == 0) mb_arrive(buf ? free1 : free0);

        // ---- tile complete: stage full 128x128 SIM + parallel ballot top-k ----
        if (c == 3) {
            const int col0 = t * TNC;
#pragma unroll
            for (int m = 0; m < 4; m++) {
                int r0 = warpM * 64 + m * 16 + gid;
#pragma unroll
                for (int n = 0; n < 4; n++) {
                    int col = warpN * 32 + n * 8 + 2 * tig;
                    *(float2*)&SIM[r0 * SIMP + col]       = make_float2(acc[m][n][0], acc[m][n][1]);
                    *(float2*)&SIM[(r0 + 8) * SIMP + col] = make_float2(acc[m][n][2], acc[m][n][3]);
                }
            }
            __syncthreads();

            // warp w scans rows w*16 .. w*16+15
#pragma unroll 2
            for (int rr = 0; rr < 16; rr++) {
                int row = wid * 16 + rr;
                float* lv = LV + row * KK;
                int*   li = LI + row * KK;
                float lv9 = lv[KK - 1];
                const float* srow = SIM + row * SIMP;
#pragma unroll
                for (int sub = 0; sub < 4; sub++) {
                    float v = srow[sub * 32 + lane];
                    unsigned msk = __ballot_sync(0xffffffffu, v > lv9);
                    while (msk) {
                        int j = __ffs(msk) - 1;
                        msk &= msk - 1;
                        float vv = __shfl_sync(0xffffffffu, v, j);
                        if (vv > lv9) {
                            if (lane == 0) {
                                int p = KK - 1;
                                while (p > 0 && lv[p - 1] < vv) {
                                    lv[p] = lv[p - 1]; li[p] = li[p - 1]; --p;
                                }
                                lv[p] = vv; li[p] = col0 + sub * 32 + j;
                                lv9 = lv[KK - 1];
                            }
                            lv9 = __shfl_sync(0xffffffffu, lv9, 0);
                        }
                    }
                }
            }
            __syncthreads();
        }
    }

    // ---- finalize: softmax + sort-by-col + write ----
    if (tid < TMR) {
        float v[KK]; int ix[KK];
#pragma unroll
        for (int k = 0; k < KK; k++) { v[k] = LV[tid * KK + k]; ix[k] = LI[tid * KK + k]; }
        float m = v[0];
        float e[KK]; float ssum = 0.0f;
#pragma unroll
        for (int k = 0; k < KK; k++) { e[k] = expf((v[k] - m) * INV_TAU); ssum += e[k]; }
        float inv = 1.0f / ssum;
#pragma unroll
        for (int a = 1; a < KK; a++) {
            int ki = ix[a]; float ke = e[a]; int p = a;
            while (p > 0 && ix[p - 1] > ki) { ix[p] = ix[p - 1]; e[p] = e[p - 1]; --p; }
            ix[p] = ki; e[p] = ke;
        }
        int gRow = xt * TMR + tid;
        size_t basev = ((size_t)b * NX + gRow) * KK;
        bool write_idx = (out_size >= 4 * NVAL);
#pragma unroll
        for (int k = 0; k < KK; k++) {
            out[basev + k] = e[k] * inv;
            if (write_idx) {
                out[(size_t)NVAL     + basev + k] = (float)b;
                out[(size_t)2 * NVAL + basev + k] = (float)gRow;
                out[(size_t)3 * NVAL + basev + k] = (float)ix[k];
            }
        }
    }
}

// ---------------- launch ----------------
extern "C" void kernel_launch(void* const* d_in, const int* in_sizes, int n_in,
                              void* d_out, int out_size) {
    const float* fx = (const float*)d_in[0];
    const float* fy = (const float*)d_in[1];
    float* out = (float*)d_out;

    int nrows = BB * NX + BB * NY;
    norm_split_kernel<<<(nrows + 7) / 8, 256>>>(fx, fy);

    cudaFuncSetAttribute(sim_mma_kernel,
                         cudaFuncAttributeMaxDynamicSharedMemorySize, SM_TOT);
    dim3 g2(NX / TMR, BB);                     // 128 CTAs
    sim_mma_kernel<<<g2, NTHR, SM_TOT>>>(out, out_size);
}

// round 15
// speedup vs baseline: 1.5085x; 1.0014x over previous
#include <cuda_runtime.h>
#include <cuda_fp16.h>
#include <cstdint>
#include <math.h>

// ---------------- problem constants ----------------
#define BB   4
#define NX   4096
#define NY   8192
#define DD   256
#define TMR  128                 // x rows per CTA
#define TNC  128                 // y cols per tile
#define KCH  64                  // k per chunk (fp16: 128B row)
#define NTIL (NY / TNC)          // 64 y tiles
#define NCHK (DD / KCH)          // 4 chunks per tile
#define CHTOT (NTIL * NCHK)      // 256 chunk iterations
#define KK   10
#define NVAL (BB * NX * KK)      // 163840
#define INV_TAU 20.0f
#define NTHR 256
#define BLKB 16384               // bytes per block (128 rows x 64 k x 2B)

// blocked + swizzled fp16-split scratch (same layout as R12/R14)
__device__ __align__(128) __half g_xh[(size_t)BB * NX * DD];
__device__ __align__(128) __half g_xl[(size_t)BB * NX * DD];
__device__ __align__(128) __half g_yh[(size_t)BB * NY * DD];
__device__ __align__(128) __half g_yl[(size_t)BB * NY * DD];

// ---------------- smem layout (bytes) ----------------
#define STG_SZ  65536
#define OFF_XH  0
#define OFF_XL  16384
#define OFF_YH  32768
#define OFF_YL  49152
#define SM_SIM  131072               // 128 x 132 floats = 67584
#define SM_LV   198656               // 128*10*4 = 5120
#define SM_LI   203776               // 5120
#define SM_CTRL 208896               // full0,full1,free0,free1
#define SM_TOT  208960
#define SIMP    132

// ---------------- helpers ----------------
static __device__ __forceinline__ uint32_t cvta_s(const void* p) {
    return (uint32_t)__cvta_generic_to_shared(p);
}
static __device__ __forceinline__ void ldm4(uint32_t* r, uint32_t addr) {
    asm volatile(
        "ldmatrix.sync.aligned.m8n8.x4.shared.b16 {%0,%1,%2,%3}, [%4];"
        : "=r"(r[0]), "=r"(r[1]), "=r"(r[2]), "=r"(r[3]) : "r"(addr));
}
static __device__ __forceinline__ void bulk16k(uint32_t dst, const void* src, uint32_t mbar) {
    asm volatile(
        "cp.async.bulk.shared::cta.global.mbarrier::complete_tx::bytes [%0], [%1], %2, [%3];"
        :: "r"(dst), "l"(src), "r"(16384u), "r"(mbar) : "memory");
}
static __device__ __forceinline__ void mb_init(uint32_t a, uint32_t c) {
    asm volatile("mbarrier.init.shared.b64 [%0], %1;" :: "r"(a), "r"(c) : "memory");
}
static __device__ __forceinline__ void mb_expect(uint32_t a, uint32_t bytes) {
    asm volatile("mbarrier.arrive.expect_tx.shared.b64 _, [%0], %1;" :: "r"(a), "r"(bytes) : "memory");
}
static __device__ __forceinline__ void mb_arrive(uint32_t a) {
    asm volatile("mbarrier.arrive.shared.b64 _, [%0];" :: "r"(a) : "memory");
}
static __device__ __forceinline__ void mb_wait(uint32_t a, uint32_t par) {
    asm volatile(
        "{\n\t.reg .pred P;\n\t"
        "WL%=:\n\t"
        "mbarrier.try_wait.parity.acquire.cta.shared::cta.b64 P, [%0], %1, 0x989680;\n\t"
        "@P bra WD%=;\n\t"
        "bra WL%=;\n\t"
        "WD%=:\n\t}"
        :: "r"(a), "r"(par) : "memory");
}
static __device__ __forceinline__ void mma16f(float* d, const uint32_t* a,
                                              uint32_t b0, uint32_t b1) {
    asm volatile(
        "mma.sync.aligned.m16n8k16.row.col.f32.f16.f16.f32 "
        "{%0,%1,%2,%3}, {%4,%5,%6,%7}, {%8,%9}, {%0,%1,%2,%3};"
        : "+f"(d[0]), "+f"(d[1]), "+f"(d[2]), "+f"(d[3])
        : "r"(a[0]), "r"(a[1]), "r"(a[2]), "r"(a[3]), "r"(b0), "r"(b1));
}

// ---------------- kernel 1: normalize + fp16-split + blocked/swizzled store ----------------
__global__ void norm_split_kernel(const float* __restrict__ fx, const float* __restrict__ fy) {
    int wid  = (blockIdx.x * blockDim.x + threadIdx.x) >> 5;
    int lane = threadIdx.x & 31;
    const int totx = BB * NX;
    if (wid >= totx + BB * NY) return;

    const float* src;
    __half *dh, *dl;
    int blk0, rit;
    if (wid < totx) {
        int b = wid / NX, r = wid % NX;
        src = fx + (size_t)wid * DD;
        dh = g_xh; dl = g_xl;
        blk0 = (b * 32 + (r >> 7)) * 4;
        rit = r & 127;
    } else {
        int r0 = wid - totx;
        int b = r0 / NY, r = r0 % NY;
        src = fy + (size_t)r0 * DD;
        dh = g_yh; dl = g_yl;
        blk0 = (b * 64 + (r >> 7)) * 4;
        rit = r & 127;
    }
    float4 a = ((const float4*)src)[lane];
    float4 b4 = ((const float4*)src)[lane + 32];
    float s = a.x*a.x + a.y*a.y + a.z*a.z + a.w*a.w
            + b4.x*b4.x + b4.y*b4.y + b4.z*b4.z + b4.w*b4.w;
#pragma unroll
    for (int off = 16; off > 0; off >>= 1) s += __shfl_xor_sync(0xffffffffu, s, off);
    float inv = 1.0f / fmaxf(sqrtf(s), 1e-12f);

    float va[4] = {a.x*inv, a.y*inv, a.z*inv, a.w*inv};
    float vb[4] = {b4.x*inv, b4.y*inv, b4.z*inv, b4.w*inv};

    __half ha[4], la[4], hb[4], lb[4];
#pragma unroll
    for (int i = 0; i < 4; i++) {
        ha[i] = __float2half_rn(va[i]);
        la[i] = __float2half_rn(va[i] - __half2float(ha[i]));
        hb[i] = __float2half_rn(vb[i]);
        lb[i] = __float2half_rn(vb[i] - __half2float(hb[i]));
    }

    int kw  = (4 * lane) & 63;
    int u   = kw >> 3;
    int hoff = kw & 7;
    size_t slotA = (size_t)(blk0 + (lane >> 4)) * 8192
                 + rit * 64 + (size_t)((u ^ (rit & 7)) * 8 + hoff);
    size_t slotB = (size_t)(blk0 + 2 + (lane >> 4)) * 8192
                 + rit * 64 + (size_t)((u ^ (rit & 7)) * 8 + hoff);

    uint2 wha, wla, whb, wlb;
    {
        __half2 p0 = __halves2half2(ha[0], ha[1]);
        __half2 p1 = __halves2half2(ha[2], ha[3]);
        wha.x = *(uint32_t*)&p0; wha.y = *(uint32_t*)&p1;
        p0 = __halves2half2(la[0], la[1]); p1 = __halves2half2(la[2], la[3]);
        wla.x = *(uint32_t*)&p0; wla.y = *(uint32_t*)&p1;
        p0 = __halves2half2(hb[0], hb[1]); p1 = __halves2half2(hb[2], hb[3]);
        whb.x = *(uint32_t*)&p0; whb.y = *(uint32_t*)&p1;
        p0 = __halves2half2(lb[0], lb[1]); p1 = __halves2half2(lb[2], lb[3]);
        wlb.x = *(uint32_t*)&p0; wlb.y = *(uint32_t*)&p1;
    }
    *(uint2*)((char*)dh + slotA * 2) = wha;
    *(uint2*)((char*)dl + slotA * 2) = wla;
    *(uint2*)((char*)dh + slotB * 2) = whb;
    *(uint2*)((char*)dl + slotB * 2) = wlb;
}

// ---------------- kernel 2: ldmatrix-fed fp16 3-pass GEMM + ballot top-k ----------------
extern __shared__ unsigned char smem_raw[];

// A: 4 x4-ldmatrix (one per m16 tile); B: 2 x4-ldmatrix (one per n16 group).
// Per-lane address precomputation done by caller; here just offset by step.
static __device__ __forceinline__ void load_frags(
    uint32_t A, uint32_t Bq, int ks,
    const uint32_t* arb,   // [4] per-m row-byte base (incl lane row)
    uint32_t brb0, uint32_t brb1,  // B row-byte bases for the 2 groups
    uint32_t akey, uint32_t ahi,   // lane&7, lane>>4  (A unit select)
    uint32_t bkey, uint32_t bhi,   // lane&7, (lane>>3)&1 (B unit select)
    uint32_t afr[4][4], uint32_t bfr[2][4])
{
    const uint32_t aoff = (((uint32_t)(2 * ks) + ahi) ^ akey) << 4;
    const uint32_t boff = (((uint32_t)(2 * ks) + bhi) ^ bkey) << 4;
#pragma unroll
    for (int m = 0; m < 4; m++) ldm4(afr[m], A + arb[m] + aoff);
    ldm4(bfr[0], Bq + brb0 + boff);
    ldm4(bfr[1], Bq + brb1 + boff);
}

__global__ void __launch_bounds__(NTHR, 1)
sim_mma_kernel(float* __restrict__ out, int out_size) {
    const int b    = blockIdx.y;
    const int xt   = blockIdx.x;
    const int tid  = threadIdx.x;
    const int wid  = tid >> 5, lane = tid & 31;
    const int warpM = wid & 1;           // 2 warps along M (64 rows each)
    const int warpN = wid >> 1;          // 4 warps along N (32 cols each)
    const int gid  = lane >> 2;
    const int tig  = lane & 3;

    uint32_t s0 = cvta_s(smem_raw);
    float* SIM = (float*)(smem_raw + SM_SIM);
    float* LV  = (float*)(smem_raw + SM_LV);
    int*   LI  = (int*)(smem_raw + SM_LI);
    const uint32_t full0 = s0 + SM_CTRL,      full1 = s0 + SM_CTRL + 8;
    const uint32_t free0 = s0 + SM_CTRL + 16, free1 = s0 + SM_CTRL + 24;

    for (int i = tid; i < TMR * KK; i += NTHR) { LV[i] = -1e38f; LI[i] = 0; }
    if (tid == 0) {
        mb_init(full0, 1); mb_init(full1, 1);
        mb_init(free0, 8); mb_init(free1, 8);
    }
    __syncthreads();

    const int xblk0 = (b * 32 + xt) * 4;
    const int yblk0 = b * 64 * 4;

    // ldmatrix per-lane bases
    // A: lanes 0-15 rows R0+lane, lanes 16-31 rows R0+(lane-16); unit 2ks + (lane>>4)
    uint32_t arb[4];
#pragma unroll
    for (int m = 0; m < 4; m++)
        arb[m] = (uint32_t)((warpM * 64 + m * 16 + (lane & 15)) * 128);
    const uint32_t akey = (uint32_t)(lane & 7);
    const uint32_t ahi  = (uint32_t)(lane >> 4);
    // B: group g rows N0 + g*16 + (lane&7) + (lane>=16 ? 8:0); unit 2ks + ((lane>>3)&1)
    const uint32_t brow = (uint32_t)((lane & 7) + ((lane >> 4) << 3));
    uint32_t brb0 = (uint32_t)((warpN * 32 + 0  + brow) * 128);
    uint32_t brb1 = (uint32_t)((warpN * 32 + 16 + brow) * 128);
    const uint32_t bkey = (uint32_t)(lane & 7);
    const uint32_t bhi  = (uint32_t)((lane >> 3) & 1);

    float acc[4][4][4];

    if (tid == 0) {
        mb_expect(full0, 65536);
        bulk16k(s0 + OFF_XH, (const char*)g_xh + (size_t)xblk0 * BLKB, full0);
        bulk16k(s0 + OFF_XL, (const char*)g_xl + (size_t)xblk0 * BLKB, full0);
        bulk16k(s0 + OFF_YH, (const char*)g_yh + (size_t)yblk0 * BLKB, full0);
        bulk16k(s0 + OFF_YL, (const char*)g_yl + (size_t)yblk0 * BLKB, full0);
    }

    for (int cc = 0; cc < CHTOT; cc++) {
        const int buf = cc & 1;
        const int c = cc & 3, t = cc >> 2;

        mb_wait(buf ? full1 : full0, (uint32_t)((cc >> 1) & 1));

        if (cc + 1 < CHTOT && tid == 0) {
            int nb = (cc + 1) & 1;
            int fi = (cc + 1) >> 1;
            if (fi >= 1) mb_wait(nb ? free1 : free0, (uint32_t)((fi - 1) & 1));
            int tn = (cc + 1) >> 2, cn = (cc + 1) & 3;
            uint32_t sb = s0 + (uint32_t)(nb * STG_SZ);
            uint32_t mbn = nb ? full1 : full0;
            mb_expect(mbn, 65536);
            bulk16k(sb + OFF_XH, (const char*)g_xh + (size_t)(xblk0 + cn) * BLKB, mbn);
            bulk16k(sb + OFF_XL, (const char*)g_xl + (size_t)(xblk0 + cn) * BLKB, mbn);
            bulk16k(sb + OFF_YH, (const char*)g_yh + (size_t)(yblk0 + tn * 4 + cn) * BLKB, mbn);
            bulk16k(sb + OFF_YL, (const char*)g_yl + (size_t)(yblk0 + tn * 4 + cn) * BLKB, mbn);
        }

        if (c == 0) {
#pragma unroll
            for (int m = 0; m < 4; m++)
#pragma unroll
                for (int n = 0; n < 4; n++)
#pragma unroll
                    for (int j = 0; j < 4; j++) acc[m][n][j] = 0.0f;
        }

        const uint32_t sb = s0 + (uint32_t)(buf * STG_SZ);
        const uint32_t Ab[3]  = {sb + OFF_XH, sb + OFF_XH, sb + OFF_XL};
        const uint32_t Bbs[3] = {sb + OFF_YH, sb + OFF_YL, sb + OFF_YH};

        // flat 12-step loop (3 pass x 4 ks), ldmatrix frags double-buffered
        uint32_t afr[2][4][4], bfr[2][2][4];
        load_frags(Ab[0], Bbs[0], 0, arb, brb0, brb1, akey, ahi, bkey, bhi,
                   afr[0], bfr[0]);
#pragma unroll
        for (int s = 0; s < 12; s++) {
            const int d = s & 1;
            if (s < 11) {
                const int sn = s + 1;
                load_frags(Ab[sn >> 2], Bbs[sn >> 2], sn & 3,
                           arb, brb0, brb1, akey, ahi, bkey, bhi,
                           afr[sn & 1], bfr[sn & 1]);
            }
#pragma unroll
            for (int m = 0; m < 4; m++)
#pragma unroll
                for (int n = 0; n < 4; n++)
                    mma16f(acc[m][n], afr[d][m],
                           bfr[d][n >> 1][(n & 1) * 2],
                           bfr[d][n >> 1][(n & 1) * 2 + 1]);
        }

        if (lane == 0) mb_arrive(buf ? free1 : free0);

        // ---- tile complete: stage full 128x128 SIM + parallel ballot top-k ----
        if (c == 3) {
            const int col0 = t * TNC;
#pragma unroll
            for (int m = 0; m < 4; m++) {
                int r0 = warpM * 64 + m * 16 + gid;
#pragma unroll
                for (int n = 0; n < 4; n++) {
                    int col = warpN * 32 + n * 8 + 2 * tig;
                    *(float2*)&SIM[r0 * SIMP + col]       = make_float2(acc[m][n][0], acc[m][n][1]);
                    *(float2*)&SIM[(r0 + 8) * SIMP + col] = make_float2(acc[m][n][2], acc[m][n][3]);
                }
            }
            __syncthreads();

            // warp w scans rows w*16 .. w*16+15
#pragma unroll 2
            for (int rr = 0; rr < 16; rr++) {
                int row = wid * 16 + rr;
                float* lv = LV + row * KK;
                int*   li = LI + row * KK;
                float lv9 = lv[KK - 1];
                const float* srow = SIM + row * SIMP;
#pragma unroll
                for (int sub = 0; sub < 4; sub++) {
                    float v = srow[sub * 32 + lane];
                    unsigned msk = __ballot_sync(0xffffffffu, v > lv9);
                    while (msk) {
                        int j = __ffs(msk) - 1;
                        msk &= msk - 1;
                        float vv = __shfl_sync(0xffffffffu, v, j);
                        if (vv > lv9) {
                            if (lane == 0) {
                                int p = KK - 1;
                                while (p > 0 && lv[p - 1] < vv) {
                                    lv[p] = lv[p - 1]; li[p] = li[p - 1]; --p;
                                }
                                lv[p] = vv; li[p] = col0 + sub * 32 + j;
                                lv9 = lv[KK - 1];
                            }
                            lv9 = __shfl_sync(0xffffffffu, lv9, 0);
                        }
                    }
                }
            }
            __syncthreads();
        }
    }

    // ---- finalize: softmax + sort-by-col + write ----
    if (tid < TMR) {
        float v[KK]; int ix[KK];
#pragma unroll
        for (int k = 0; k < KK; k++) { v[k] = LV[tid * KK + k]; ix[k] = LI[tid * KK + k]; }
        float m = v[0];
        float e[KK]; float ssum = 0.0f;
#pragma unroll
        for (int k = 0; k < KK; k++) { e[k] = expf((v[k] - m) * INV_TAU); ssum += e[k]; }
        float inv = 1.0f / ssum;
#pragma unroll
        for (int a = 1; a < KK; a++) {
            int ki = ix[a]; float ke = e[a]; int p = a;
            while (p > 0 && ix[p - 1] > ki) { ix[p] = ix[p - 1]; e[p] = e[p - 1]; --p; }
            ix[p] = ki; e[p] = ke;
        }
        int gRow = xt * TMR + tid;
        size_t basev = ((size_t)b * NX + gRow) * KK;
        bool write_idx = (out_size >= 4 * NVAL);
#pragma unroll
        for (int k = 0; k < KK; k++) {
            out[basev + k] = e[k] * inv;
            if (write_idx) {
                out[(size_t)NVAL     + basev + k] = (float)b;
                out[(size_t)2 * NVAL + basev + k] = (float)gRow;
                out[(size_t)3 * NVAL + basev + k] = (float)ix[k];
            }
        }
    }
}

// ---------------- launch ----------------
extern "C" void kernel_launch(void* const* d_in, const int* in_sizes, int n_in,
                              void* d_out, int out_size) {
    const float* fx = (const float*)d_in[0];
    const float* fy = (const float*)d_in[1];
    float* out = (float*)d_out;

    int nrows = BB * NX + BB * NY;
    norm_split_kernel<<<(nrows + 7) / 8, 256>>>(fx, fy);

    cudaFuncSetAttribute(sim_mma_kernel,
                         cudaFuncAttributeMaxDynamicSharedMemorySize, SM_TOT);
    dim3 g2(NX / TMR, BB);                     // 128 CTAs
    sim_mma_kernel<<<g2, NTHR, SM_TOT>>>(out, out_size);
}

// round 16
// speedup vs baseline: 1.9161x; 1.2702x over previous
#include <cuda_runtime.h>
#include <cuda_fp16.h>
#include <cstdint>
#include <math.h>

// ---------------- problem constants ----------------
#define BB   4
#define NX   4096
#define NY   8192
#define DD   256
#define TMR  128                 // x rows per CTA
#define TNC  128                 // y cols per tile
#define KCH  64                  // k per chunk (fp16: 128B row)
#define NTIL (NY / TNC)          // 64 y tiles
#define NCHK (DD / KCH)          // 4 chunks per tile
#define CHTOT (NTIL * NCHK)      // 256 chunk iterations
#define KK   10
#define NVAL (BB * NX * KK)      // 163840
#define INV_TAU 20.0f
#define NTHR 512
#define BLKB 16384               // bytes per block (128 rows x 64 k x 2B)

// blocked + swizzled fp16-split scratch (same layout as R12/R14/R15)
__device__ __align__(128) __half g_xh[(size_t)BB * NX * DD];
__device__ __align__(128) __half g_xl[(size_t)BB * NX * DD];
__device__ __align__(128) __half g_yh[(size_t)BB * NY * DD];
__device__ __align__(128) __half g_yl[(size_t)BB * NY * DD];

// ---------------- smem layout (bytes) ----------------
#define STG_SZ  65536
#define OFF_XH  0
#define OFF_XL  16384
#define OFF_YH  32768
#define OFF_YL  49152
#define SM_SIM  131072               // 128 x 132 floats = 67584
#define SM_LV   198656               // 128*10*4 = 5120
#define SM_LI   203776               // 5120
#define SM_CTRL 208896               // full0,full1,free0,free1
#define SM_TOT  208960
#define SIMP    132

// ---------------- helpers ----------------
static __device__ __forceinline__ uint32_t cvta_s(const void* p) {
    return (uint32_t)__cvta_generic_to_shared(p);
}
static __device__ __forceinline__ void ldm4(uint32_t* r, uint32_t addr) {
    asm volatile(
        "ldmatrix.sync.aligned.m8n8.x4.shared.b16 {%0,%1,%2,%3}, [%4];"
        : "=r"(r[0]), "=r"(r[1]), "=r"(r[2]), "=r"(r[3]) : "r"(addr));
}
static __device__ __forceinline__ void bulk16k(uint32_t dst, const void* src, uint32_t mbar) {
    asm volatile(
        "cp.async.bulk.shared::cta.global.mbarrier::complete_tx::bytes [%0], [%1], %2, [%3];"
        :: "r"(dst), "l"(src), "r"(16384u), "r"(mbar) : "memory");
}
static __device__ __forceinline__ void mb_init(uint32_t a, uint32_t c) {
    asm volatile("mbarrier.init.shared.b64 [%0], %1;" :: "r"(a), "r"(c) : "memory");
}
static __device__ __forceinline__ void mb_expect(uint32_t a, uint32_t bytes) {
    asm volatile("mbarrier.arrive.expect_tx.shared.b64 _, [%0], %1;" :: "r"(a), "r"(bytes) : "memory");
}
static __device__ __forceinline__ void mb_arrive(uint32_t a) {
    asm volatile("mbarrier.arrive.shared.b64 _, [%0];" :: "r"(a) : "memory");
}
static __device__ __forceinline__ void mb_wait(uint32_t a, uint32_t par) {
    asm volatile(
        "{\n\t.reg .pred P;\n\t"
        "WL%=:\n\t"
        "mbarrier.try_wait.parity.acquire.cta.shared::cta.b64 P, [%0], %1, 0x989680;\n\t"
        "@P bra WD%=;\n\t"
        "bra WL%=;\n\t"
        "WD%=:\n\t}"
        :: "r"(a), "r"(par) : "memory");
}
static __device__ __forceinline__ void mma16f(float* d, const uint32_t* a,
                                              uint32_t b0, uint32_t b1) {
    asm volatile(
        "mma.sync.aligned.m16n8k16.row.col.f32.f16.f16.f32 "
        "{%0,%1,%2,%3}, {%4,%5,%6,%7}, {%8,%9}, {%0,%1,%2,%3};"
        : "+f"(d[0]), "+f"(d[1]), "+f"(d[2]), "+f"(d[3])
        : "r"(a[0]), "r"(a[1]), "r"(a[2]), "r"(a[3]), "r"(b0), "r"(b1));
}

// ---------------- kernel 1: normalize + fp16-split + blocked/swizzled store ----------------
__global__ void norm_split_kernel(const float* __restrict__ fx, const float* __restrict__ fy) {
    int wid  = (blockIdx.x * blockDim.x + threadIdx.x) >> 5;
    int lane = threadIdx.x & 31;
    const int totx = BB * NX;
    if (wid >= totx + BB * NY) return;

    const float* src;
    __half *dh, *dl;
    int blk0, rit;
    if (wid < totx) {
        int b = wid / NX, r = wid % NX;
        src = fx + (size_t)wid * DD;
        dh = g_xh; dl = g_xl;
        blk0 = (b * 32 + (r >> 7)) * 4;
        rit = r & 127;
    } else {
        int r0 = wid - totx;
        int b = r0 / NY, r = r0 % NY;
        src = fy + (size_t)r0 * DD;
        dh = g_yh; dl = g_yl;
        blk0 = (b * 64 + (r >> 7)) * 4;
        rit = r & 127;
    }
    float4 a = ((const float4*)src)[lane];
    float4 b4 = ((const float4*)src)[lane + 32];
    float s = a.x*a.x + a.y*a.y + a.z*a.z + a.w*a.w
            + b4.x*b4.x + b4.y*b4.y + b4.z*b4.z + b4.w*b4.w;
#pragma unroll
    for (int off = 16; off > 0; off >>= 1) s += __shfl_xor_sync(0xffffffffu, s, off);
    float inv = 1.0f / fmaxf(sqrtf(s), 1e-12f);

    float va[4] = {a.x*inv, a.y*inv, a.z*inv, a.w*inv};
    float vb[4] = {b4.x*inv, b4.y*inv, b4.z*inv, b4.w*inv};

    __half ha[4], la[4], hb[4], lb[4];
#pragma unroll
    for (int i = 0; i < 4; i++) {
        ha[i] = __float2half_rn(va[i]);
        la[i] = __float2half_rn(va[i] - __half2float(ha[i]));
        hb[i] = __float2half_rn(vb[i]);
        lb[i] = __float2half_rn(vb[i] - __half2float(hb[i]));
    }

    int kw  = (4 * lane) & 63;
    int u   = kw >> 3;
    int hoff = kw & 7;
    size_t slotA = (size_t)(blk0 + (lane >> 4)) * 8192
                 + rit * 64 + (size_t)((u ^ (rit & 7)) * 8 + hoff);
    size_t slotB = (size_t)(blk0 + 2 + (lane >> 4)) * 8192
                 + rit * 64 + (size_t)((u ^ (rit & 7)) * 8 + hoff);

    uint2 wha, wla, whb, wlb;
    {
        __half2 p0 = __halves2half2(ha[0], ha[1]);
        __half2 p1 = __halves2half2(ha[2], ha[3]);
        wha.x = *(uint32_t*)&p0; wha.y = *(uint32_t*)&p1;
        p0 = __halves2half2(la[0], la[1]); p1 = __halves2half2(la[2], la[3]);
        wla.x = *(uint32_t*)&p0; wla.y = *(uint32_t*)&p1;
        p0 = __halves2half2(hb[0], hb[1]); p1 = __halves2half2(hb[2], hb[3]);
        whb.x = *(uint32_t*)&p0; whb.y = *(uint32_t*)&p1;
        p0 = __halves2half2(lb[0], lb[1]); p1 = __halves2half2(lb[2], lb[3]);
        wlb.x = *(uint32_t*)&p0; wlb.y = *(uint32_t*)&p1;
    }
    *(uint2*)((char*)dh + slotA * 2) = wha;
    *(uint2*)((char*)dl + slotA * 2) = wla;
    *(uint2*)((char*)dh + slotB * 2) = whb;
    *(uint2*)((char*)dl + slotB * 2) = wlb;
}

// ---------------- kernel 2: 512-thread ldmatrix fp16 3-pass GEMM + ballot top-k ----------------
extern __shared__ unsigned char smem_raw[];

// 32x32 warp tile: A = 2 ldmatrix.x4 (2 m16 tiles), B = 2 ldmatrix.x4 (2 n16 groups)
static __device__ __forceinline__ void load_frags(
    uint32_t A, uint32_t Bq, int ks,
    uint32_t arb0, uint32_t arb1,
    uint32_t brb0, uint32_t brb1,
    uint32_t akey, uint32_t ahi,
    uint32_t bkey, uint32_t bhi,
    uint32_t afr[2][4], uint32_t bfr[2][4])
{
    const uint32_t aoff = (((uint32_t)(2 * ks) + ahi) ^ akey) << 4;
    const uint32_t boff = (((uint32_t)(2 * ks) + bhi) ^ bkey) << 4;
    ldm4(afr[0], A + arb0 + aoff);
    ldm4(afr[1], A + arb1 + aoff);
    ldm4(bfr[0], Bq + brb0 + boff);
    ldm4(bfr[1], Bq + brb1 + boff);
}

__global__ void __launch_bounds__(NTHR, 1)
sim_mma_kernel(float* __restrict__ out, int out_size) {
    const int b    = blockIdx.y;
    const int xt   = blockIdx.x;
    const int tid  = threadIdx.x;
    const int wid  = tid >> 5, lane = tid & 31;
    const int warpM = wid & 3;           // 4 warps along M (32 rows each)
    const int warpN = wid >> 2;          // 4 warps along N (32 cols each)
    const int gid  = lane >> 2;
    const int tig  = lane & 3;

    uint32_t s0 = cvta_s(smem_raw);
    float* SIM = (float*)(smem_raw + SM_SIM);
    float* LV  = (float*)(smem_raw + SM_LV);
    int*   LI  = (int*)(smem_raw + SM_LI);
    const uint32_t full0 = s0 + SM_CTRL,      full1 = s0 + SM_CTRL + 8;
    const uint32_t free0 = s0 + SM_CTRL + 16, free1 = s0 + SM_CTRL + 24;

    for (int i = tid; i < TMR * KK; i += NTHR) { LV[i] = -1e38f; LI[i] = 0; }
    if (tid == 0) {
        mb_init(full0, 1); mb_init(full1, 1);
        mb_init(free0, 16); mb_init(free1, 16);
    }
    __syncthreads();

    const int xblk0 = (b * 32 + xt) * 4;
    const int yblk0 = b * 64 * 4;

    // ldmatrix per-lane bases (32x32 warp tile)
    uint32_t arb0 = (uint32_t)((warpM * 32 + 0  + (lane & 15)) * 128);
    uint32_t arb1 = (uint32_t)((warpM * 32 + 16 + (lane & 15)) * 128);
    const uint32_t akey = (uint32_t)(lane & 7);
    const uint32_t ahi  = (uint32_t)(lane >> 4);
    const uint32_t brow = (uint32_t)((lane & 7) + ((lane >> 4) << 3));
    uint32_t brb0 = (uint32_t)((warpN * 32 + 0  + brow) * 128);
    uint32_t brb1 = (uint32_t)((warpN * 32 + 16 + brow) * 128);
    const uint32_t bkey = (uint32_t)(lane & 7);
    const uint32_t bhi  = (uint32_t)((lane >> 3) & 1);

    float acc[2][4][4];

    if (tid == 0) {
        mb_expect(full0, 65536);
        bulk16k(s0 + OFF_XH, (const char*)g_xh + (size_t)xblk0 * BLKB, full0);
        bulk16k(s0 + OFF_XL, (const char*)g_xl + (size_t)xblk0 * BLKB, full0);
        bulk16k(s0 + OFF_YH, (const char*)g_yh + (size_t)yblk0 * BLKB, full0);
        bulk16k(s0 + OFF_YL, (const char*)g_yl + (size_t)yblk0 * BLKB, full0);
    }

    for (int cc = 0; cc < CHTOT; cc++) {
        const int buf = cc & 1;
        const int c = cc & 3, t = cc >> 2;

        mb_wait(buf ? full1 : full0, (uint32_t)((cc >> 1) & 1));

        if (cc + 1 < CHTOT && tid == 0) {
            int nb = (cc + 1) & 1;
            int fi = (cc + 1) >> 1;
            if (fi >= 1) mb_wait(nb ? free1 : free0, (uint32_t)((fi - 1) & 1));
            int tn = (cc + 1) >> 2, cn = (cc + 1) & 3;
            uint32_t sb = s0 + (uint32_t)(nb * STG_SZ);
            uint32_t mbn = nb ? full1 : full0;
            mb_expect(mbn, 65536);
            bulk16k(sb + OFF_XH, (const char*)g_xh + (size_t)(xblk0 + cn) * BLKB, mbn);
            bulk16k(sb + OFF_XL, (const char*)g_xl + (size_t)(xblk0 + cn) * BLKB, mbn);
            bulk16k(sb + OFF_YH, (const char*)g_yh + (size_t)(yblk0 + tn * 4 + cn) * BLKB, mbn);
            bulk16k(sb + OFF_YL, (const char*)g_yl + (size_t)(yblk0 + tn * 4 + cn) * BLKB, mbn);
        }

        if (c == 0) {
#pragma unroll
            for (int m = 0; m < 2; m++)
#pragma unroll
                for (int n = 0; n < 4; n++)
#pragma unroll
                    for (int j = 0; j < 4; j++) acc[m][n][j] = 0.0f;
        }

        const uint32_t sb = s0 + (uint32_t)(buf * STG_SZ);
        const uint32_t Ab[3]  = {sb + OFF_XH, sb + OFF_XH, sb + OFF_XL};
        const uint32_t Bbs[3] = {sb + OFF_YH, sb + OFF_YL, sb + OFF_YH};

        // flat 12-step loop (3 pass x 4 ks), ldmatrix frags double-buffered
        uint32_t afr[2][2][4], bfr[2][2][4];
        load_frags(Ab[0], Bbs[0], 0, arb0, arb1, brb0, brb1,
                   akey, ahi, bkey, bhi, afr[0], bfr[0]);
#pragma unroll
        for (int s = 0; s < 12; s++) {
            const int d = s & 1;
            if (s < 11) {
                const int sn = s + 1;
                load_frags(Ab[sn >> 2], Bbs[sn >> 2], sn & 3,
                           arb0, arb1, brb0, brb1, akey, ahi, bkey, bhi,
                           afr[sn & 1], bfr[sn & 1]);
            }
#pragma unroll
            for (int m = 0; m < 2; m++)
#pragma unroll
                for (int n = 0; n < 4; n++)
                    mma16f(acc[m][n], afr[d][m],
                           bfr[d][n >> 1][(n & 1) * 2],
                           bfr[d][n >> 1][(n & 1) * 2 + 1]);
        }

        if (lane == 0) mb_arrive(buf ? free1 : free0);

        // ---- tile complete: stage full 128x128 SIM + parallel ballot top-k ----
        if (c == 3) {
            const int col0 = t * TNC;
#pragma unroll
            for (int m = 0; m < 2; m++) {
                int r0 = warpM * 32 + m * 16 + gid;
#pragma unroll
                for (int n = 0; n < 4; n++) {
                    int col = warpN * 32 + n * 8 + 2 * tig;
                    *(float2*)&SIM[r0 * SIMP + col]       = make_float2(acc[m][n][0], acc[m][n][1]);
                    *(float2*)&SIM[(r0 + 8) * SIMP + col] = make_float2(acc[m][n][2], acc[m][n][3]);
                }
            }
            __syncthreads();

            // warp w scans rows w*8 .. w*8+7
#pragma unroll 2
            for (int rr = 0; rr < 8; rr++) {
                int row = wid * 8 + rr;
                float* lv = LV + row * KK;
                int*   li = LI + row * KK;
                float lv9 = lv[KK - 1];
                const float* srow = SIM + row * SIMP;
#pragma unroll
                for (int sub = 0; sub < 4; sub++) {
                    float v = srow[sub * 32 + lane];
                    unsigned msk = __ballot_sync(0xffffffffu, v > lv9);
                    while (msk) {
                        int j = __ffs(msk) - 1;
                        msk &= msk - 1;
                        float vv = __shfl_sync(0xffffffffu, v, j);
                        if (vv > lv9) {
                            if (lane == 0) {
                                int p = KK - 1;
                                while (p > 0 && lv[p - 1] < vv) {
                                    lv[p] = lv[p - 1]; li[p] = li[p - 1]; --p;
                                }
                                lv[p] = vv; li[p] = col0 + sub * 32 + j;
                                lv9 = lv[KK - 1];
                            }
                            lv9 = __shfl_sync(0xffffffffu, lv9, 0);
                        }
                    }
                }
            }
            __syncthreads();
        }
    }

    // ---- finalize: softmax + sort-by-col + write ----
    if (tid < TMR) {
        float v[KK]; int ix[KK];
#pragma unroll
        for (int k = 0; k < KK; k++) { v[k] = LV[tid * KK + k]; ix[k] = LI[tid * KK + k]; }
        float m = v[0];
        float e[KK]; float ssum = 0.0f;
#pragma unroll
        for (int k = 0; k < KK; k++) { e[k] = expf((v[k] - m) * INV_TAU); ssum += e[k]; }
        float inv = 1.0f / ssum;
#pragma unroll
        for (int a = 1; a < KK; a++) {
            int ki = ix[a]; float ke = e[a]; int p = a;
            while (p > 0 && ix[p - 1] > ki) { ix[p] = ix[p - 1]; e[p] = e[p - 1]; --p; }
            ix[p] = ki; e[p] = ke;
        }
        int gRow = xt * TMR + tid;
        size_t basev = ((size_t)b * NX + gRow) * KK;
        bool write_idx = (out_size >= 4 * NVAL);
#pragma unroll
        for (int k = 0; k < KK; k++) {
            out[basev + k] = e[k] * inv;
            if (write_idx) {
                out[(size_t)NVAL     + basev + k] = (float)b;
                out[(size_t)2 * NVAL + basev + k] = (float)gRow;
                out[(size_t)3 * NVAL + basev + k] = (float)ix[k];
            }
        }
    }
}

// ---------------- launch ----------------
extern "C" void kernel_launch(void* const* d_in, const int* in_sizes, int n_in,
                              void* d_out, int out_size) {
    const float* fx = (const float*)d_in[0];
    const float* fy = (const float*)d_in[1];
    float* out = (float*)d_out;

    int nrows = BB * NX + BB * NY;
    norm_split_kernel<<<(nrows + 7) / 8, 256>>>(fx, fy);

    cudaFuncSetAttribute(sim_mma_kernel,
                         cudaFuncAttributeMaxDynamicSharedMemorySize, SM_TOT);
    dim3 g2(NX / TMR, BB);                     // 128 CTAs
    sim_mma_kernel<<<g2, NTHR, SM_TOT>>>(out, out_size);
}

// round 17
// speedup vs baseline: 1.9674x; 1.0268x over previous
#include <cuda_runtime.h>
#include <cuda_fp16.h>
#include <cstdint>
#include <math.h>

// ---------------- problem constants ----------------
#define BB   4
#define NX   4096
#define NY   8192
#define DD   256
#define TMR  128                 // x rows per CTA
#define TNC  128                 // y cols per tile
#define KCH  64                  // k per chunk (fp16: 128B row)
#define NTIL (NY / TNC)          // 64 y tiles
#define NCHK (DD / KCH)          // 4 chunks per tile
#define CHTOT (NTIL * NCHK)      // 256 chunk iterations
#define KK   10
#define NVAL (BB * NX * KK)      // 163840
#define INV_TAU 20.0f
#define NTHR 512
#define BLKB 16384               // bytes per block (128 rows x 64 k x 2B)

// blocked + swizzled fp16-split scratch (same layout as R12..R16)
__device__ __align__(128) __half g_xh[(size_t)BB * NX * DD];
__device__ __align__(128) __half g_xl[(size_t)BB * NX * DD];
__device__ __align__(128) __half g_yh[(size_t)BB * NY * DD];
__device__ __align__(128) __half g_yl[(size_t)BB * NY * DD];

// ---------------- smem layout (bytes) ----------------
#define STG_SZ  65536
#define OFF_XH  0
#define OFF_XL  16384
#define OFF_YH  32768
#define OFF_YL  49152
#define SM_SIM  131072               // 128 x 132 floats = 67584
#define SM_LV   198656               // 128*10*4 = 5120
#define SM_LI   203776               // 5120
#define SM_CTRL 208896               // full0,full1,free0,free1
#define SM_TOT  208960
#define SIMP    132

// ---------------- helpers ----------------
static __device__ __forceinline__ uint32_t cvta_s(const void* p) {
    return (uint32_t)__cvta_generic_to_shared(p);
}
static __device__ __forceinline__ void ldm4(uint32_t* r, uint32_t addr) {
    asm volatile(
        "ldmatrix.sync.aligned.m8n8.x4.shared.b16 {%0,%1,%2,%3}, [%4];"
        : "=r"(r[0]), "=r"(r[1]), "=r"(r[2]), "=r"(r[3]) : "r"(addr));
}
static __device__ __forceinline__ void bulk16k(uint32_t dst, const void* src, uint32_t mbar) {
    asm volatile(
        "cp.async.bulk.shared::cta.global.mbarrier::complete_tx::bytes [%0], [%1], %2, [%3];"
        :: "r"(dst), "l"(src), "r"(16384u), "r"(mbar) : "memory");
}
static __device__ __forceinline__ void mb_init(uint32_t a, uint32_t c) {
    asm volatile("mbarrier.init.shared.b64 [%0], %1;" :: "r"(a), "r"(c) : "memory");
}
static __device__ __forceinline__ void mb_expect(uint32_t a, uint32_t bytes) {
    asm volatile("mbarrier.arrive.expect_tx.shared.b64 _, [%0], %1;" :: "r"(a), "r"(bytes) : "memory");
}
static __device__ __forceinline__ void mb_arrive(uint32_t a) {
    asm volatile("mbarrier.arrive.shared.b64 _, [%0];" :: "r"(a) : "memory");
}
static __device__ __forceinline__ void mb_wait(uint32_t a, uint32_t par) {
    asm volatile(
        "{\n\t.reg .pred P;\n\t"
        "WL%=:\n\t"
        "mbarrier.try_wait.parity.acquire.cta.shared::cta.b64 P, [%0], %1, 0x989680;\n\t"
        "@P bra WD%=;\n\t"
        "bra WL%=;\n\t"
        "WD%=:\n\t}"
        :: "r"(a), "r"(par) : "memory");
}
static __device__ __forceinline__ void mma16f(float* d, const uint32_t* a,
                                              uint32_t b0, uint32_t b1) {
    asm volatile(
        "mma.sync.aligned.m16n8k16.row.col.f32.f16.f16.f32 "
        "{%0,%1,%2,%3}, {%4,%5,%6,%7}, {%8,%9}, {%0,%1,%2,%3};"
        : "+f"(d[0]), "+f"(d[1]), "+f"(d[2]), "+f"(d[3])
        : "r"(a[0]), "r"(a[1]), "r"(a[2]), "r"(a[3]), "r"(b0), "r"(b1));
}

// ---------------- kernel 1: normalize + fp16-split + blocked/swizzled store ----------------
__global__ void norm_split_kernel(const float* __restrict__ fx, const float* __restrict__ fy) {
    int wid  = (blockIdx.x * blockDim.x + threadIdx.x) >> 5;
    int lane = threadIdx.x & 31;
    const int totx = BB * NX;
    if (wid >= totx + BB * NY) return;

    const float* src;
    __half *dh, *dl;
    int blk0, rit;
    if (wid < totx) {
        int b = wid / NX, r = wid % NX;
        src = fx + (size_t)wid * DD;
        dh = g_xh; dl = g_xl;
        blk0 = (b * 32 + (r >> 7)) * 4;
        rit = r & 127;
    } else {
        int r0 = wid - totx;
        int b = r0 / NY, r = r0 % NY;
        src = fy + (size_t)r0 * DD;
        dh = g_yh; dl = g_yl;
        blk0 = (b * 64 + (r >> 7)) * 4;
        rit = r & 127;
    }
    float4 a = ((const float4*)src)[lane];
    float4 b4 = ((const float4*)src)[lane + 32];
    float s = a.x*a.x + a.y*a.y + a.z*a.z + a.w*a.w
            + b4.x*b4.x + b4.y*b4.y + b4.z*b4.z + b4.w*b4.w;
#pragma unroll
    for (int off = 16; off > 0; off >>= 1) s += __shfl_xor_sync(0xffffffffu, s, off);
    float inv = 1.0f / fmaxf(sqrtf(s), 1e-12f);

    float va[4] = {a.x*inv, a.y*inv, a.z*inv, a.w*inv};
    float vb[4] = {b4.x*inv, b4.y*inv, b4.z*inv, b4.w*inv};

    __half ha[4], la[4], hb[4], lb[4];
#pragma unroll
    for (int i = 0; i < 4; i++) {
        ha[i] = __float2half_rn(va[i]);
        la[i] = __float2half_rn(va[i] - __half2float(ha[i]));
        hb[i] = __float2half_rn(vb[i]);
        lb[i] = __float2half_rn(vb[i] - __half2float(hb[i]));
    }

    int kw  = (4 * lane) & 63;
    int u   = kw >> 3;
    int hoff = kw & 7;
    size_t slotA = (size_t)(blk0 + (lane >> 4)) * 8192
                 + rit * 64 + (size_t)((u ^ (rit & 7)) * 8 + hoff);
    size_t slotB = (size_t)(blk0 + 2 + (lane >> 4)) * 8192
                 + rit * 64 + (size_t)((u ^ (rit & 7)) * 8 + hoff);

    uint2 wha, wla, whb, wlb;
    {
        __half2 p0 = __halves2half2(ha[0], ha[1]);
        __half2 p1 = __halves2half2(ha[2], ha[3]);
        wha.x = *(uint32_t*)&p0; wha.y = *(uint32_t*)&p1;
        p0 = __halves2half2(la[0], la[1]); p1 = __halves2half2(la[2], la[3]);
        wla.x = *(uint32_t*)&p0; wla.y = *(uint32_t*)&p1;
        p0 = __halves2half2(hb[0], hb[1]); p1 = __halves2half2(hb[2], hb[3]);
        whb.x = *(uint32_t*)&p0; whb.y = *(uint32_t*)&p1;
        p0 = __halves2half2(lb[0], lb[1]); p1 = __halves2half2(lb[2], lb[3]);
        wlb.x = *(uint32_t*)&p0; wlb.y = *(uint32_t*)&p1;
    }
    *(uint2*)((char*)dh + slotA * 2) = wha;
    *(uint2*)((char*)dl + slotA * 2) = wla;
    *(uint2*)((char*)dh + slotB * 2) = whb;
    *(uint2*)((char*)dl + slotB * 2) = wlb;
}

// ---------------- kernel 2: ks-major fp16 3-product GEMM + ballot top-k ----------------
extern __shared__ unsigned char smem_raw[];

__global__ void __launch_bounds__(NTHR, 1)
sim_mma_kernel(float* __restrict__ out, int out_size) {
    const int b    = blockIdx.y;
    const int xt   = blockIdx.x;
    const int tid  = threadIdx.x;
    const int wid  = tid >> 5, lane = tid & 31;
    const int warpM = wid & 3;           // 4 warps along M (32 rows each)
    const int warpN = wid >> 2;          // 4 warps along N (32 cols each)
    const int gid  = lane >> 2;
    const int tig  = lane & 3;

    uint32_t s0 = cvta_s(smem_raw);
    float* SIM = (float*)(smem_raw + SM_SIM);
    float* LV  = (float*)(smem_raw + SM_LV);
    int*   LI  = (int*)(smem_raw + SM_LI);
    const uint32_t full0 = s0 + SM_CTRL,      full1 = s0 + SM_CTRL + 8;
    const uint32_t free0 = s0 + SM_CTRL + 16, free1 = s0 + SM_CTRL + 24;

    for (int i = tid; i < TMR * KK; i += NTHR) { LV[i] = -1e38f; LI[i] = 0; }
    if (tid == 0) {
        mb_init(full0, 1); mb_init(full1, 1);
        mb_init(free0, 16); mb_init(free1, 16);
    }
    __syncthreads();

    const int xblk0 = (b * 32 + xt) * 4;
    const int yblk0 = b * 64 * 4;

    // ldmatrix per-lane bases (32x32 warp tile)
    uint32_t arb0 = (uint32_t)((warpM * 32 + 0  + (lane & 15)) * 128);
    uint32_t arb1 = (uint32_t)((warpM * 32 + 16 + (lane & 15)) * 128);
    const uint32_t akey = (uint32_t)(lane & 7);
    const uint32_t ahi  = (uint32_t)(lane >> 4);
    const uint32_t brow = (uint32_t)((lane & 7) + ((lane >> 4) << 3));
    uint32_t brb0 = (uint32_t)((warpN * 32 + 0  + brow) * 128);
    uint32_t brb1 = (uint32_t)((warpN * 32 + 16 + brow) * 128);
    const uint32_t bkey = (uint32_t)(lane & 7);
    const uint32_t bhi  = (uint32_t)((lane >> 3) & 1);

    float acc[2][4][4];

    if (tid == 0) {
        mb_expect(full0, 65536);
        bulk16k(s0 + OFF_XH, (const char*)g_xh + (size_t)xblk0 * BLKB, full0);
        bulk16k(s0 + OFF_XL, (const char*)g_xl + (size_t)xblk0 * BLKB, full0);
        bulk16k(s0 + OFF_YH, (const char*)g_yh + (size_t)yblk0 * BLKB, full0);
        bulk16k(s0 + OFF_YL, (const char*)g_yl + (size_t)yblk0 * BLKB, full0);
    }

    for (int cc = 0; cc < CHTOT; cc++) {
        const int buf = cc & 1;
        const int c = cc & 3, t = cc >> 2;

        mb_wait(buf ? full1 : full0, (uint32_t)((cc >> 1) & 1));

        if (cc + 1 < CHTOT && tid == 0) {
            int nb = (cc + 1) & 1;
            int fi = (cc + 1) >> 1;
            if (fi >= 1) mb_wait(nb ? free1 : free0, (uint32_t)((fi - 1) & 1));
            int tn = (cc + 1) >> 2, cn = (cc + 1) & 3;
            uint32_t sb2 = s0 + (uint32_t)(nb * STG_SZ);
            uint32_t mbn = nb ? full1 : full0;
            mb_expect(mbn, 65536);
            bulk16k(sb2 + OFF_XH, (const char*)g_xh + (size_t)(xblk0 + cn) * BLKB, mbn);
            bulk16k(sb2 + OFF_XL, (const char*)g_xl + (size_t)(xblk0 + cn) * BLKB, mbn);
            bulk16k(sb2 + OFF_YH, (const char*)g_yh + (size_t)(yblk0 + tn * 4 + cn) * BLKB, mbn);
            bulk16k(sb2 + OFF_YL, (const char*)g_yl + (size_t)(yblk0 + tn * 4 + cn) * BLKB, mbn);
        }

        if (c == 0) {
#pragma unroll
            for (int m = 0; m < 2; m++)
#pragma unroll
                for (int n = 0; n < 4; n++)
#pragma unroll
                    for (int j = 0; j < 4; j++) acc[m][n][j] = 0.0f;
        }

        const uint32_t sb = s0 + (uint32_t)(buf * STG_SZ);

        // ks-major: per k-step load all 4 operand sets once, issue hh + hl + lh
#pragma unroll
        for (int ks = 0; ks < 4; ks++) {
            const uint32_t aoff = (((uint32_t)(2 * ks) + ahi) ^ akey) << 4;
            const uint32_t boff = (((uint32_t)(2 * ks) + bhi) ^ bkey) << 4;
            uint32_t ah[2][4], al[2][4], bh[2][4], bl[2][4];
            ldm4(ah[0], sb + OFF_XH + arb0 + aoff);
            ldm4(ah[1], sb + OFF_XH + arb1 + aoff);
            ldm4(bh[0], sb + OFF_YH + brb0 + boff);
            ldm4(bh[1], sb + OFF_YH + brb1 + boff);
            ldm4(al[0], sb + OFF_XL + arb0 + aoff);
            ldm4(al[1], sb + OFF_XL + arb1 + aoff);
            ldm4(bl[0], sb + OFF_YL + brb0 + boff);
            ldm4(bl[1], sb + OFF_YL + brb1 + boff);
            // hh
#pragma unroll
            for (int m = 0; m < 2; m++)
#pragma unroll
                for (int n = 0; n < 4; n++)
                    mma16f(acc[m][n], ah[m],
                           bh[n >> 1][(n & 1) * 2], bh[n >> 1][(n & 1) * 2 + 1]);
            // hl
#pragma unroll
            for (int m = 0; m < 2; m++)
#pragma unroll
                for (int n = 0; n < 4; n++)
                    mma16f(acc[m][n], ah[m],
                           bl[n >> 1][(n & 1) * 2], bl[n >> 1][(n & 1) * 2 + 1]);
            // lh
#pragma unroll
            for (int m = 0; m < 2; m++)
#pragma unroll
                for (int n = 0; n < 4; n++)
                    mma16f(acc[m][n], al[m],
                           bh[n >> 1][(n & 1) * 2], bh[n >> 1][(n & 1) * 2 + 1]);
        }

        if (lane == 0) mb_arrive(buf ? free1 : free0);

        // ---- tile complete: stage full 128x128 SIM + parallel ballot top-k ----
        if (c == 3) {
            const int col0 = t * TNC;
#pragma unroll
            for (int m = 0; m < 2; m++) {
                int r0 = warpM * 32 + m * 16 + gid;
#pragma unroll
                for (int n = 0; n < 4; n++) {
                    int col = warpN * 32 + n * 8 + 2 * tig;
                    *(float2*)&SIM[r0 * SIMP + col]       = make_float2(acc[m][n][0], acc[m][n][1]);
                    *(float2*)&SIM[(r0 + 8) * SIMP + col] = make_float2(acc[m][n][2], acc[m][n][3]);
                }
            }
            __syncthreads();

            // warp w scans rows w*8 .. w*8+7
#pragma unroll 2
            for (int rr = 0; rr < 8; rr++) {
                int row = wid * 8 + rr;
                float* lv = LV + row * KK;
                int*   li = LI + row * KK;
                float lv9 = lv[KK - 1];
                const float* srow = SIM + row * SIMP;
#pragma unroll
                for (int sub = 0; sub < 4; sub++) {
                    float v = srow[sub * 32 + lane];
                    unsigned msk = __ballot_sync(0xffffffffu, v > lv9);
                    while (msk) {
                        int j = __ffs(msk) - 1;
                        msk &= msk - 1;
                        float vv = __shfl_sync(0xffffffffu, v, j);
                        if (vv > lv9) {
                            if (lane == 0) {
                                int p = KK - 1;
                                while (p > 0 && lv[p - 1] < vv) {
                                    lv[p] = lv[p - 1]; li[p] = li[p - 1]; --p;
                                }
                                lv[p] = vv; li[p] = col0 + sub * 32 + j;
                                lv9 = lv[KK - 1];
                            }
                            lv9 = __shfl_sync(0xffffffffu, lv9, 0);
                        }
                    }
                }
            }
            __syncthreads();
        }
    }

    // ---- finalize: softmax + sort-by-col + write ----
    if (tid < TMR) {
        float v[KK]; int ix[KK];
#pragma unroll
        for (int k = 0; k < KK; k++) { v[k] = LV[tid * KK + k]; ix[k] = LI[tid * KK + k]; }
        float m = v[0];
        float e[KK]; float ssum = 0.0f;
#pragma unroll
        for (int k = 0; k < KK; k++) { e[k] = expf((v[k] - m) * INV_TAU); ssum += e[k]; }
        float inv = 1.0f / ssum;
#pragma unroll
        for (int a = 1; a < KK; a++) {
            int ki = ix[a]; float ke = e[a]; int p = a;
            while (p > 0 && ix[p - 1] > ki) { ix[p] = ix[p - 1]; e[p] = e[p - 1]; --p; }
            ix[p] = ki; e[p] = ke;
        }
        int gRow = xt * TMR + tid;
        size_t basev = ((size_t)b * NX + gRow) * KK;
        bool write_idx = (out_size >= 4 * NVAL);
#pragma unroll
        for (int k = 0; k < KK; k++) {
            out[basev + k] = e[k] * inv;
            if (write_idx) {
                out[(size_t)NVAL     + basev + k] = (float)b;
                out[(size_t)2 * NVAL + basev + k] = (float)gRow;
                out[(size_t)3 * NVAL + basev + k] = (float)ix[k];
            }
        }
    }
}

// ---------------- launch ----------------
extern "C" void kernel_launch(void* const* d_in, const int* in_sizes, int n_in,
                              void* d_out, int out_size) {
    const float* fx = (const float*)d_in[0];
    const float* fy = (const float*)d_in[1];
    float* out = (float*)d_out;

    int nrows = BB * NX + BB * NY;
    norm_split_kernel<<<(nrows + 7) / 8, 256>>>(fx, fy);

    cudaFuncSetAttribute(sim_mma_kernel,
                         cudaFuncAttributeMaxDynamicSharedMemorySize, SM_TOT);
    dim3 g2(NX / TMR, BB);                     // 128 CTAs
    sim_mma_kernel<<<g2, NTHR, SM_TOT>>>(out, out_size);
}